// round 15
// baseline (speedup 1.0000x reference)
#include <cuda_runtime.h>
#include <cuda_fp16.h>
#include <math.h>
#include <stdint.h>

#define BATCH 2
#define SEQ 2048
#define HIDDEN 2048
#define NH 16
#define KVH 4
#define HD 128
#define MTOT (BATCH*SEQ)
#define QKVW 3072
#define KOFF 2048
#define VOFF 2560
#define SSCALE 0.08838834764831845f

// scratch (no allocation allowed -> device globals), all fp16
__device__ __align__(16) __half g_qkv[MTOT*QKVW];
__device__ __align__(16) __half g_ctx[MTOT*HIDDEN];
__device__ __align__(16) __half g_hs[MTOT*HIDDEN];
__device__ __align__(16) __half g_wqkv[QKVW*HIDDEN];
__device__ __align__(16) __half g_wo[HIDDEN*HIDDEN];

// ===========================================================================
// helpers
// ===========================================================================
__device__ __forceinline__ uint32_t smem_u32(const void* p) {
    uint32_t a;
    asm("{ .reg .u64 t; cvta.to.shared.u64 t, %1; cvt.u32.u64 %0, t; }"
        : "=r"(a) : "l"(p));
    return a;
}
__device__ __forceinline__ void cp_async16(uint32_t saddr, const void* gaddr) {
    asm volatile("cp.async.cg.shared.global [%0], [%1], 16;"
                 :: "r"(saddr), "l"(gaddr));
}
__device__ __forceinline__ void cp_commit() {
    asm volatile("cp.async.commit_group;" ::: "memory");
}
__device__ __forceinline__ void cp_wait2() {
    asm volatile("cp.async.wait_group 2;" ::: "memory");
}
__device__ __forceinline__ void cp_wait0() {
    asm volatile("cp.async.wait_group 0;" ::: "memory");
}
// D += A*B : fp16 m16n8k16, fp32 accumulate
__device__ __forceinline__ void mma_f16(float* d, const uint32_t* a, const uint32_t* b) {
    asm volatile(
        "mma.sync.aligned.m16n8k16.row.col.f32.f16.f16.f32 "
        "{%0,%1,%2,%3}, {%4,%5,%6,%7}, {%8,%9}, {%0,%1,%2,%3};"
        : "+f"(d[0]), "+f"(d[1]), "+f"(d[2]), "+f"(d[3])
        : "r"(a[0]), "r"(a[1]), "r"(a[2]), "r"(a[3]), "r"(b[0]), "r"(b[1]));
}
#define LDSM4(r0,r1,r2,r3,addr)                                              \
    asm volatile("ldmatrix.sync.aligned.m8n8.x4.shared.b16 {%0,%1,%2,%3}, [%4];" \
        : "=r"(r0), "=r"(r1), "=r"(r2), "=r"(r3) : "r"(addr))
#define LDSM4T(r0,r1,r2,r3,addr)                                             \
    asm volatile("ldmatrix.sync.aligned.m8n8.x4.trans.shared.b16 {%0,%1,%2,%3}, [%4];" \
        : "=r"(r0), "=r"(r1), "=r"(r2), "=r"(r3) : "r"(addr))

// ===========================================================================
// fused fp16 conversion pass: hs -> g_hs, [Wq|Wk|Wv] -> g_wqkv, Wo -> g_wo
// ===========================================================================
#define N4_HS  (MTOT*HIDDEN/4)
#define N4_WQ  (HIDDEN*HIDDEN/4)
#define N4_WKV (KVH*HD*HIDDEN/4)
#define N4_TOT (N4_HS + 2*N4_WQ + 2*N4_WKV)

__global__ void round5_kernel(
    const float* __restrict__ hs, const float* __restrict__ wq,
    const float* __restrict__ wk, const float* __restrict__ wv,
    const float* __restrict__ wo,
    __half* __restrict__ dhs, __half* __restrict__ dwqkv,
    __half* __restrict__ dwo)
{
    int i = blockIdx.x * 256 + threadIdx.x;
    if (i >= N4_TOT) return;
    const float* src; __half* dst; int j = i;
    if (j < N4_HS)                  { src = hs; dst = dhs; }
    else if ((j -= N4_HS) < N4_WQ)  { src = wq; dst = dwqkv; }
    else if ((j -= N4_WQ) < N4_WKV) { src = wk; dst = dwqkv + (size_t)KOFF*HIDDEN; }
    else if ((j -= N4_WKV) < N4_WKV){ src = wv; dst = dwqkv + (size_t)VOFF*HIDDEN; }
    else { j -= N4_WKV; src = wo; dst = dwo; }
    float4 v = ((const float4*)src)[j];
    ((__half2*)dst)[2*j]   = __floats2half2_rn(v.x, v.y);
    ((__half2*)dst)[2*j+1] = __floats2half2_rn(v.z, v.w);
}

// ===========================================================================
// fp16 mma.sync GEMM with ldmatrix. CTA 128x256, BK=64 halves, 4-stage
// cp.async, 256 threads (8 warps, 2x4 grid, warp tile 64x64 -> 1.0 wf/MMA).
// ===========================================================================
#define BKH 64
#define APADH 72
#define STAGE_HALVES ((128+256)*APADH)
#define NSTAGE 4
#define GEMM_SMEM (NSTAGE*STAGE_HALVES*2)

__global__ void __launch_bounds__(256, 1) gemm_mma(
    const __half* __restrict__ A, const __half* __restrict__ B,
    void* __restrict__ Cv, int M, int N, int K, int store_half)
{
    extern __shared__ __half smh[];
    const uint32_t smb = smem_u32(smh);

    const int tid  = threadIdx.x;
    const int warp = tid >> 5, lane = tid & 31;
    const int wm = warp >> 2, wn = warp & 3;   // 2 x 4 grid, tile 64x64
    const int m0 = blockIdx.y << 7, n0 = blockIdx.x << 8;
    const int q = lane >> 2, r = lane & 3;

    const int lmt = lane >> 3, lmr = lane & 7;
    const uint32_t lmoff = (uint32_t)((((lmt & 1) << 3 | lmr) * APADH + ((lmt >> 1) << 3)) * 2);

    float acc[4][8][4];
#pragma unroll
    for (int i = 0; i < 4; i++)
#pragma unroll
        for (int j = 0; j < 8; j++)
            acc[i][j][0]=acc[i][j][1]=acc[i][j][2]=acc[i][j][3]=0.f;

    const int arow0 = tid >> 3, ach = (tid & 7) << 3;

#define LOAD_TILE(s, kt) do {                                               \
    const uint32_t sA_ = smb + (uint32_t)(s)*STAGE_HALVES*2;                \
    const uint32_t sB_ = sA_ + 128*APADH*2;                                 \
    const int koff = (kt) * BKH;                                            \
    _Pragma("unroll")                                                       \
    for (int l_ = 0; l_ < 4; l_++) {                                        \
        int row = arow0 + l_*32;                                            \
        cp_async16(sA_ + (uint32_t)(row*APADH + ach)*2,                     \
                   A + (size_t)(m0 + row) * K + koff + ach);                \
    }                                                                       \
    _Pragma("unroll")                                                       \
    for (int l_ = 0; l_ < 8; l_++) {                                        \
        int row = arow0 + l_*32;                                            \
        cp_async16(sB_ + (uint32_t)(row*APADH + ach)*2,                     \
                   B + (size_t)(n0 + row) * K + koff + ach);                \
    } } while (0)

    const int KT = K / BKH;
    LOAD_TILE(0, 0); cp_commit();
    LOAD_TILE(1, 1); cp_commit();
    LOAD_TILE(2, 2); cp_commit();
    cp_wait2();
    __syncthreads();

    for (int kt = 0; kt < KT; kt++) {
        const int nxt = kt + 3;
        if (nxt < KT) {
            LOAD_TILE(nxt & 3, nxt);
        }
        cp_commit();

        const int cs = kt & 3;
        const uint32_t sAb = smb + (uint32_t)cs*STAGE_HALVES*2;
        const uint32_t sBb = sAb + 128*APADH*2;

#pragma unroll
        for (int ks = 0; ks < 4; ks++) {
            const uint32_t kk2 = (uint32_t)(ks*32);
            uint32_t afr[4][4], bfr[8][2];
#pragma unroll
            for (int i = 0; i < 4; i++)
                LDSM4(afr[i][0], afr[i][1], afr[i][2], afr[i][3],
                      sAb + (uint32_t)((wm*64 + i*16)*APADH*2) + lmoff + kk2);
#pragma unroll
            for (int jj = 0; jj < 4; jj++)
                LDSM4(bfr[2*jj][0], bfr[2*jj+1][0], bfr[2*jj][1], bfr[2*jj+1][1],
                      sBb + (uint32_t)((wn*64 + jj*16)*APADH*2) + lmoff + kk2);
#pragma unroll
            for (int i = 0; i < 4; i++)
#pragma unroll
                for (int j = 0; j < 8; j++)
                    mma_f16(acc[i][j], afr[i], bfr[j]);
        }

        cp_wait2();
        __syncthreads();
    }

    if (store_half) {
        __half* C = (__half*)Cv;
#pragma unroll
        for (int i = 0; i < 4; i++) {
            const int row = m0 + wm*64 + i*16 + q;
#pragma unroll
            for (int j = 0; j < 8; j++) {
                const int col = n0 + wn*64 + j*8 + 2*r;
                *(__half2*)(C + (size_t)row * N + col) =
                    __floats2half2_rn(acc[i][j][0], acc[i][j][1]);
                *(__half2*)(C + (size_t)(row+8) * N + col) =
                    __floats2half2_rn(acc[i][j][2], acc[i][j][3]);
            }
        }
    } else {
        float* C = (float*)Cv;
#pragma unroll
        for (int i = 0; i < 4; i++) {
            const int row = m0 + wm*64 + i*16 + q;
#pragma unroll
            for (int j = 0; j < 8; j++) {
                const int col = n0 + wn*64 + j*8 + 2*r;
                float2 lo; lo.x = acc[i][j][0]; lo.y = acc[i][j][1];
                float2 hi; hi.x = acc[i][j][2]; hi.y = acc[i][j][3];
                *(float2*)(C + (size_t)row * N + col)     = lo;
                *(float2*)(C + (size_t)(row+8) * N + col) = hi;
            }
        }
    }
#undef LOAD_TILE
}

// ---------------------------------------------------------------------------
// fused RoPE on fp16 q (with sscale folded) and k, in-place
// ---------------------------------------------------------------------------
#define ROPE_NQ (MTOT*NH*64)
#define ROPE_NK (MTOT*KVH*64)
#define ROPE_TOT (ROPE_NQ + ROPE_NK)

__global__ void rope_kernel(__half* __restrict__ qkv,
                            const float* __restrict__ cs,
                            const float* __restrict__ sn)
{
    int idx = blockIdx.x * 256 + threadIdx.x;
    if (idx < ROPE_NQ) {
        int d = idx & 63;
        int h = (idx >> 6) % NH;
        int t = idx / (NH << 6);
        __half* row = qkv + (size_t)t * QKVW + h * HD;
        int s = t & (SEQ - 1);
        float x1 = __half2float(row[d]), x2 = __half2float(row[d + 64]);
        row[d]      = __float2half((x1 * cs[s*HD + d]      - x2 * sn[s*HD + d])      * SSCALE);
        row[d + 64] = __float2half((x2 * cs[s*HD + d + 64] + x1 * sn[s*HD + d + 64]) * SSCALE);
    } else if ((idx -= ROPE_NQ) < ROPE_NK) {
        int d = idx & 63;
        int h = (idx >> 6) % KVH;
        int t = idx / (KVH << 6);
        __half* row = qkv + (size_t)t * QKVW + KOFF + h * HD;
        int s = t & (SEQ - 1);
        float x1 = __half2float(row[d]), x2 = __half2float(row[d + 64]);
        row[d]      = __float2half(x1 * cs[s*HD + d]      - x2 * sn[s*HD + d]);
        row[d + 64] = __float2half(x2 * cs[s*HD + d + 64] + x1 * sn[s*HD + d + 64]);
    }
}

// ---------------------------------------------------------------------------
// Flash attention v2 (FA2 layout): fp16 mma, register-resident P.
// Br=Bc=128, D=128. 256 threads, 8 warps; each warp owns 16 full rows.
// K/V double-buffered cp.async; V via ldmatrix.trans; kb/vb fragment
// double-buffering to hide LDS latency at 2 warps/SMSP.
// ---------------------------------------------------------------------------
#define FH 136
#define TILE_B (128*FH*2)                 // 34816 bytes
#define SQ_B 0
#define SK_B(s) (TILE_B*(1 + 2*(s)))
#define SV_B(s) (TILE_B*(2 + 2*(s)))
#define FLASH_SMEM (5*TILE_B)

__global__ void __launch_bounds__(256, 1) flash_mma_kernel(
    const __half* __restrict__ qkv, __half* __restrict__ ctx)
{
    extern __shared__ char smc[];
    const uint32_t smb = smem_u32(smc);

    const int b = blockIdx.z, h = blockIdx.y;
    const int qb = (int)gridDim.x - 1 - (int)blockIdx.x;   // long CTAs first
    const int kh = h >> 2;
    const int tid = threadIdx.x;
    const int warp = tid >> 5, lane = tid & 31;
    const int qd = lane >> 2, r4 = lane & 3;

    const int lmt = lane >> 3, lmr = lane & 7;
    const uint32_t lmoff  = (uint32_t)(((((lmt & 1) << 3) | lmr) * FH + ((lmt >> 1) << 3)) * 2);
    const uint32_t lmoffT = (uint32_t)(((lmr + ((lmt >> 1) << 3)) * FH + ((lmt & 1) << 3)) * 2);

    const int grow0 = qb * 128;

    // ---- prologue: Q + K0 + V0 in one group ----
    {
        const __half* qb_ = qkv + (size_t)(b*SEQ + qb*128) * QKVW + h * HD;
        const __half* kb_ = qkv + (size_t)(b*SEQ) * QKVW + KOFF + kh * HD;
        const __half* vb_ = qkv + (size_t)(b*SEQ) * QKVW + VOFF + kh * HD;
#pragma unroll
        for (int l = 0; l < 8; l++) {
            int idx = tid + l*256;
            int row = idx >> 4, ch = (idx & 15) << 3;
            uint32_t so = (uint32_t)((row*FH + ch)*2);
            cp_async16(smb + SQ_B    + so, qb_ + (size_t)row * QKVW + ch);
            cp_async16(smb + SK_B(0) + so, kb_ + (size_t)row * QKVW + ch);
            cp_async16(smb + SV_B(0) + so, vb_ + (size_t)row * QKVW + ch);
        }
        cp_commit();
    }

    float m_r0 = -1e30f, m_r1 = -1e30f, l_r0 = 0.f, l_r1 = 0.f;
    float oacc[16][4];
#pragma unroll
    for (int j = 0; j < 16; j++)
        oacc[j][0]=oacc[j][1]=oacc[j][2]=oacc[j][3]=0.f;

    for (int jb = 0; jb <= qb; jb++) {
        cp_wait0();
        __syncthreads();

        if (jb < qb) {
            const int nb = (jb + 1) & 1;
            const __half* kb_ = qkv + (size_t)(b*SEQ + (jb+1)*128) * QKVW + KOFF + kh * HD;
            const __half* vb_ = qkv + (size_t)(b*SEQ + (jb+1)*128) * QKVW + VOFF + kh * HD;
            const uint32_t skn = smb + (uint32_t)SK_B(nb);
            const uint32_t svn = smb + (uint32_t)SV_B(nb);
#pragma unroll
            for (int l = 0; l < 8; l++) {
                int idx = tid + l*256;
                int row = idx >> 4, ch = (idx & 15) << 3;
                uint32_t so = (uint32_t)((row*FH + ch)*2);
                cp_async16(skn + so, kb_ + (size_t)row * QKVW + ch);
                cp_async16(svn + so, vb_ + (size_t)row * QKVW + ch);
            }
            cp_commit();
        }

        const uint32_t sK = smb + (uint32_t)SK_B(jb & 1);
        const uint32_t sV = smb + (uint32_t)SV_B(jb & 1);

        // ---- QK: warp rows warp*16..+15 x all 128 cols, kb double-buffered ----
        float sc[16][4];
#pragma unroll
        for (int j = 0; j < 16; j++)
            sc[j][0]=sc[j][1]=sc[j][2]=sc[j][3]=0.f;

        const uint32_t aQ0 = smb + (uint32_t)(SQ_B + (warp*16)*FH*2) + lmoff;
#pragma unroll
        for (int ks = 0; ks < 8; ks++) {
            const uint32_t kk2 = (uint32_t)(ks*32);
            uint32_t qa[4];
            LDSM4(qa[0], qa[1], qa[2], qa[3], aQ0 + kk2);
            uint32_t kb2[2][2][2];
            LDSM4(kb2[0][0][0], kb2[0][1][0], kb2[0][0][1], kb2[0][1][1],
                  sK + lmoff + kk2);
#pragma unroll
            for (int jt = 0; jt < 8; jt++) {
                const int cur = jt & 1;
                if (jt < 7)
                    LDSM4(kb2[cur^1][0][0], kb2[cur^1][1][0],
                          kb2[cur^1][0][1], kb2[cur^1][1][1],
                          sK + (uint32_t)(((jt+1)*16)*FH*2) + lmoff + kk2);
                mma_f16(sc[jt*2],   qa, kb2[cur][0]);
                mma_f16(sc[jt*2+1], qa, kb2[cur][1]);
            }
        }

        // ---- causal mask ----
        const int col0 = jb * 128;
        if (jb == qb) {
            const int rg0 = grow0 + warp*16 + qd;
#pragma unroll
            for (int j = 0; j < 16; j++) {
                int cg = col0 + j*8 + 2*r4;
                if (cg     > rg0)     sc[j][0] = -1e30f;
                if (cg + 1 > rg0)     sc[j][1] = -1e30f;
                if (cg     > rg0 + 8) sc[j][2] = -1e30f;
                if (cg + 1 > rg0 + 8) sc[j][3] = -1e30f;
            }
        }

        // ---- warp-local softmax ----
        float mx0 = sc[0][0], mx1 = sc[0][2];
#pragma unroll
        for (int j = 0; j < 16; j++) {
            mx0 = fmaxf(mx0, fmaxf(sc[j][0], sc[j][1]));
            mx1 = fmaxf(mx1, fmaxf(sc[j][2], sc[j][3]));
        }
        mx0 = fmaxf(mx0, __shfl_xor_sync(0xffffffffu, mx0, 1));
        mx0 = fmaxf(mx0, __shfl_xor_sync(0xffffffffu, mx0, 2));
        mx1 = fmaxf(mx1, __shfl_xor_sync(0xffffffffu, mx1, 1));
        mx1 = fmaxf(mx1, __shfl_xor_sync(0xffffffffu, mx1, 2));
        const float mn0 = fmaxf(m_r0, mx0);
        const float mn1 = fmaxf(m_r1, mx1);
        const float corr0 = __expf(m_r0 - mn0);
        const float corr1 = __expf(m_r1 - mn1);
        m_r0 = mn0; m_r1 = mn1;

        float ls0 = 0.f, ls1 = 0.f;
#pragma unroll
        for (int j = 0; j < 16; j++) {
            sc[j][0] = __expf(sc[j][0] - mn0); ls0 += sc[j][0];
            sc[j][1] = __expf(sc[j][1] - mn0); ls0 += sc[j][1];
            sc[j][2] = __expf(sc[j][2] - mn1); ls1 += sc[j][2];
            sc[j][3] = __expf(sc[j][3] - mn1); ls1 += sc[j][3];
        }
        ls0 += __shfl_xor_sync(0xffffffffu, ls0, 1);
        ls0 += __shfl_xor_sync(0xffffffffu, ls0, 2);
        ls1 += __shfl_xor_sync(0xffffffffu, ls1, 1);
        ls1 += __shfl_xor_sync(0xffffffffu, ls1, 2);
        l_r0 = l_r0 * corr0 + ls0;
        l_r1 = l_r1 * corr1 + ls1;
#pragma unroll
        for (int j = 0; j < 16; j++) {
            oacc[j][0] *= corr0; oacc[j][1] *= corr0;
            oacc[j][2] *= corr1; oacc[j][3] *= corr1;
        }

        // ---- PV: A = P (registers), B = V via ldmatrix.trans, vb dbuf ----
#pragma unroll
        for (int c = 0; c < 8; c++) {
            uint32_t pa[4];
            {
                __half2 t0 = __floats2half2_rn(sc[2*c][0],   sc[2*c][1]);
                __half2 t1 = __floats2half2_rn(sc[2*c][2],   sc[2*c][3]);
                __half2 t2 = __floats2half2_rn(sc[2*c+1][0], sc[2*c+1][1]);
                __half2 t3 = __floats2half2_rn(sc[2*c+1][2], sc[2*c+1][3]);
                pa[0] = *(uint32_t*)&t0; pa[1] = *(uint32_t*)&t1;
                pa[2] = *(uint32_t*)&t2; pa[3] = *(uint32_t*)&t3;
            }
            const uint32_t vrow = sV + (uint32_t)((c*16)*FH*2) + lmoffT;
            uint32_t vb2[2][2][2];
            LDSM4T(vb2[0][0][0], vb2[0][1][0], vb2[0][0][1], vb2[0][1][1], vrow);
#pragma unroll
            for (int dt = 0; dt < 8; dt++) {
                const int cur = dt & 1;
                if (dt < 7)
                    LDSM4T(vb2[cur^1][0][0], vb2[cur^1][1][0],
                           vb2[cur^1][0][1], vb2[cur^1][1][1],
                           vrow + (uint32_t)(((dt+1)*16)*2));
                mma_f16(oacc[dt*2],   pa, vb2[cur][0]);
                mma_f16(oacc[dt*2+1], pa, vb2[cur][1]);
            }
        }
    }

    // ---- epilogue: normalize, store fp16 ctx ----
    const float inv0 = 1.f / l_r0;
    const float inv1 = 1.f / l_r1;
    const int row = warp*16 + qd;
    __half* d0 = ctx + ((size_t)(b*SEQ + grow0 + row  ) * NH + h) * HD;
    __half* d1 = ctx + ((size_t)(b*SEQ + grow0 + row+8) * NH + h) * HD;
#pragma unroll
    for (int j = 0; j < 16; j++) {
        const int col = j*8 + 2*r4;
        *(__half2*)(d0 + col) = __floats2half2_rn(oacc[j][0]*inv0, oacc[j][1]*inv0);
        *(__half2*)(d1 + col) = __floats2half2_rn(oacc[j][2]*inv1, oacc[j][3]*inv1);
    }
}

// ---------------------------------------------------------------------------
extern "C" void kernel_launch(void* const* d_in, const int* in_sizes, int n_in,
                              void* d_out, int out_size)
{
    const float* hs   = (const float*)d_in[0];
    const float* cosp = (const float*)d_in[1];
    const float* sinp = (const float*)d_in[2];
    const float* Wq   = (const float*)d_in[3];
    const float* Wk   = (const float*)d_in[4];
    const float* Wv   = (const float*)d_in[5];
    const float* Wo   = (const float*)d_in[6];
    float* out = (float*)d_out;

    __half *qkv, *ctx, *hs_h, *wqkv, *wo;
    cudaGetSymbolAddress((void**)&qkv,  g_qkv);
    cudaGetSymbolAddress((void**)&ctx,  g_ctx);
    cudaGetSymbolAddress((void**)&hs_h, g_hs);
    cudaGetSymbolAddress((void**)&wqkv, g_wqkv);
    cudaGetSymbolAddress((void**)&wo,   g_wo);

    cudaFuncSetAttribute(gemm_mma, cudaFuncAttributeMaxDynamicSharedMemorySize,
                         (int)GEMM_SMEM);
    cudaFuncSetAttribute(flash_mma_kernel, cudaFuncAttributeMaxDynamicSharedMemorySize,
                         (int)FLASH_SMEM);

    const int M = MTOT;  // 4096

    // 1) fp32 -> fp16 conversion of all inputs
    round5_kernel<<<(N4_TOT + 255)/256, 256>>>(hs, Wq, Wk, Wv, Wo,
                                               hs_h, wqkv, wo);

    // 2) fused QKV projection (fp16 MMA, fp16 output; 64x64 warp tiles)
    gemm_mma<<<dim3(QKVW/256, M/128), 256, GEMM_SMEM>>>(hs_h, wqkv, qkv,
                                                        M, QKVW, HIDDEN, 1);

    // 3) fused RoPE on q (scaled) and k
    rope_kernel<<<(ROPE_TOT + 255)/256, 256>>>(qkv, cosp, sinp);

    // 4) attention (FA2: register P, warp softmax, dbuf K/V + dbuf fragments)
    flash_mma_kernel<<<dim3(SEQ/128, NH, BATCH), 256, FLASH_SMEM>>>(qkv, ctx);

    // 5) output projection (fp16 MMA, fp32 output)
    gemm_mma<<<dim3(HIDDEN/256, M/128), 256, GEMM_SMEM>>>(ctx, wo, out,
                                                          M, HIDDEN, HIDDEN, 0);
}

// round 16
// speedup vs baseline: 1.0094x; 1.0094x over previous
#include <cuda_runtime.h>
#include <cuda_fp16.h>
#include <math.h>
#include <stdint.h>

#define BATCH 2
#define SEQ 2048
#define HIDDEN 2048
#define NH 16
#define KVH 4
#define HD 128
#define MTOT (BATCH*SEQ)
#define QKVW 3072
#define KOFF 2048
#define VOFF 2560
#define SSCALE 0.08838834764831845f

// scratch (no allocation allowed -> device globals), all fp16
__device__ __align__(16) __half g_qkv[MTOT*QKVW];
__device__ __align__(16) __half g_ctx[MTOT*HIDDEN];
__device__ __align__(16) __half g_hs[MTOT*HIDDEN];
__device__ __align__(16) __half g_wqkv[QKVW*HIDDEN];
__device__ __align__(16) __half g_wo[HIDDEN*HIDDEN];

// ===========================================================================
// helpers
// ===========================================================================
__device__ __forceinline__ uint32_t smem_u32(const void* p) {
    uint32_t a;
    asm("{ .reg .u64 t; cvta.to.shared.u64 t, %1; cvt.u32.u64 %0, t; }"
        : "=r"(a) : "l"(p));
    return a;
}
__device__ __forceinline__ void cp_async16(uint32_t saddr, const void* gaddr) {
    asm volatile("cp.async.cg.shared.global [%0], [%1], 16;"
                 :: "r"(saddr), "l"(gaddr));
}
__device__ __forceinline__ void cp_commit() {
    asm volatile("cp.async.commit_group;" ::: "memory");
}
__device__ __forceinline__ void cp_wait1() {
    asm volatile("cp.async.wait_group 1;" ::: "memory");
}
__device__ __forceinline__ void cp_wait0() {
    asm volatile("cp.async.wait_group 0;" ::: "memory");
}
// D += A*B : fp16 m16n8k16, fp32 accumulate
__device__ __forceinline__ void mma_f16(float* d, const uint32_t* a, const uint32_t* b) {
    asm volatile(
        "mma.sync.aligned.m16n8k16.row.col.f32.f16.f16.f32 "
        "{%0,%1,%2,%3}, {%4,%5,%6,%7}, {%8,%9}, {%0,%1,%2,%3};"
        : "+f"(d[0]), "+f"(d[1]), "+f"(d[2]), "+f"(d[3])
        : "r"(a[0]), "r"(a[1]), "r"(a[2]), "r"(a[3]), "r"(b[0]), "r"(b[1]));
}
#define LDSM4(r0,r1,r2,r3,addr)                                              \
    asm volatile("ldmatrix.sync.aligned.m8n8.x4.shared.b16 {%0,%1,%2,%3}, [%4];" \
        : "=r"(r0), "=r"(r1), "=r"(r2), "=r"(r3) : "r"(addr))
#define LDSM4T(r0,r1,r2,r3,addr)                                             \
    asm volatile("ldmatrix.sync.aligned.m8n8.x4.trans.shared.b16 {%0,%1,%2,%3}, [%4];" \
        : "=r"(r0), "=r"(r1), "=r"(r2), "=r"(r3) : "r"(addr))

// ===========================================================================
// fused fp16 conversion pass: hs -> g_hs, [Wq|Wk|Wv] -> g_wqkv, Wo -> g_wo
// ===========================================================================
#define N4_HS  (MTOT*HIDDEN/4)
#define N4_WQ  (HIDDEN*HIDDEN/4)
#define N4_WKV (KVH*HD*HIDDEN/4)
#define N4_TOT (N4_HS + 2*N4_WQ + 2*N4_WKV)

__global__ void round5_kernel(
    const float* __restrict__ hs, const float* __restrict__ wq,
    const float* __restrict__ wk, const float* __restrict__ wv,
    const float* __restrict__ wo,
    __half* __restrict__ dhs, __half* __restrict__ dwqkv,
    __half* __restrict__ dwo)
{
    int i = blockIdx.x * 256 + threadIdx.x;
    if (i >= N4_TOT) return;
    const float* src; __half* dst; int j = i;
    if (j < N4_HS)                  { src = hs; dst = dhs; }
    else if ((j -= N4_HS) < N4_WQ)  { src = wq; dst = dwqkv; }
    else if ((j -= N4_WQ) < N4_WKV) { src = wk; dst = dwqkv + (size_t)KOFF*HIDDEN; }
    else if ((j -= N4_WKV) < N4_WKV){ src = wv; dst = dwqkv + (size_t)VOFF*HIDDEN; }
    else { j -= N4_WKV; src = wo; dst = dwo; }
    float4 v = ((const float4*)src)[j];
    ((__half2*)dst)[2*j]   = __floats2half2_rn(v.x, v.y);
    ((__half2*)dst)[2*j+1] = __floats2half2_rn(v.z, v.w);
}

// ===========================================================================
// fp16 mma.sync GEMM with ldmatrix. CTA 128x128, BK=64 halves, 3-stage
// cp.async, 256 threads (8 warps, 2x4 grid, warp tile 64x32).
// smem 110.6KB -> 2 CTAs/SM; __launch_bounds__(256,2) caps regs at 128.
// N multiple of 128, K multiple of 64.
// ===========================================================================
#define BKH 64
#define APADH 72
#define STAGE_HALVES ((128+128)*APADH)
#define NSTAGE 3
#define GEMM_SMEM (NSTAGE*STAGE_HALVES*2)

__global__ void __launch_bounds__(256, 2) gemm_mma(
    const __half* __restrict__ A, const __half* __restrict__ B,
    void* __restrict__ Cv, int M, int N, int K, int store_half)
{
    extern __shared__ __half smh[];
    const uint32_t smb = smem_u32(smh);

    const int tid  = threadIdx.x;
    const int warp = tid >> 5, lane = tid & 31;
    const int wm = warp >> 2, wn = warp & 3;   // 2 x 4 grid, warp tile 64x32
    const int m0 = blockIdx.y << 7, n0 = blockIdx.x << 7;
    const int q = lane >> 2, r = lane & 3;

    const int lmt = lane >> 3, lmr = lane & 7;
    const uint32_t lmoff = (uint32_t)((((lmt & 1) << 3 | lmr) * APADH + ((lmt >> 1) << 3)) * 2);

    float acc[4][4][4];
#pragma unroll
    for (int i = 0; i < 4; i++)
#pragma unroll
        for (int j = 0; j < 4; j++)
            acc[i][j][0]=acc[i][j][1]=acc[i][j][2]=acc[i][j][3]=0.f;

    const int arow0 = tid >> 3, ach = (tid & 7) << 3;   // 32 rows/pass, 16B chunks

#define LOAD_TILE(s, kt) do {                                               \
    const uint32_t sA_ = smb + (uint32_t)(s)*STAGE_HALVES*2;                \
    const uint32_t sB_ = sA_ + 128*APADH*2;                                 \
    const int koff = (kt) * BKH;                                            \
    _Pragma("unroll")                                                       \
    for (int l_ = 0; l_ < 4; l_++) {                                        \
        int row = arow0 + l_*32;                                            \
        cp_async16(sA_ + (uint32_t)(row*APADH + ach)*2,                     \
                   A + (size_t)(m0 + row) * K + koff + ach);                \
        cp_async16(sB_ + (uint32_t)(row*APADH + ach)*2,                     \
                   B + (size_t)(n0 + row) * K + koff + ach);                \
    } } while (0)

    const int KT = K / BKH;
    LOAD_TILE(0, 0); cp_commit();
    LOAD_TILE(1, 1); cp_commit();
    cp_wait1();
    __syncthreads();

    for (int kt = 0; kt < KT; kt++) {
        const int nxt = kt + 2;
        if (nxt < KT) {
            int s = nxt - (nxt/NSTAGE)*NSTAGE;
            LOAD_TILE(s, nxt);
        }
        cp_commit();

        const int cs = kt - (kt/NSTAGE)*NSTAGE;
        const uint32_t sAb = smb + (uint32_t)cs*STAGE_HALVES*2;
        const uint32_t sBb = sAb + 128*APADH*2;

#pragma unroll
        for (int ks = 0; ks < 4; ks++) {
            const uint32_t kk2 = (uint32_t)(ks*32);
            uint32_t afr[4][4], bfr[4][2];
#pragma unroll
            for (int i = 0; i < 4; i++)
                LDSM4(afr[i][0], afr[i][1], afr[i][2], afr[i][3],
                      sAb + (uint32_t)((wm*64 + i*16)*APADH*2) + lmoff + kk2);
            LDSM4(bfr[0][0], bfr[1][0], bfr[0][1], bfr[1][1],
                  sBb + (uint32_t)((wn*32)*APADH*2) + lmoff + kk2);
            LDSM4(bfr[2][0], bfr[3][0], bfr[2][1], bfr[3][1],
                  sBb + (uint32_t)((wn*32 + 16)*APADH*2) + lmoff + kk2);
#pragma unroll
            for (int i = 0; i < 4; i++)
#pragma unroll
                for (int j = 0; j < 4; j++)
                    mma_f16(acc[i][j], afr[i], bfr[j]);
        }

        cp_wait1();
        __syncthreads();
    }

    if (store_half) {
        __half* C = (__half*)Cv;
#pragma unroll
        for (int i = 0; i < 4; i++) {
            const int row = m0 + wm*64 + i*16 + q;
#pragma unroll
            for (int j = 0; j < 4; j++) {
                const int col = n0 + wn*32 + j*8 + 2*r;
                *(__half2*)(C + (size_t)row * N + col) =
                    __floats2half2_rn(acc[i][j][0], acc[i][j][1]);
                *(__half2*)(C + (size_t)(row+8) * N + col) =
                    __floats2half2_rn(acc[i][j][2], acc[i][j][3]);
            }
        }
    } else {
        float* C = (float*)Cv;
#pragma unroll
        for (int i = 0; i < 4; i++) {
            const int row = m0 + wm*64 + i*16 + q;
#pragma unroll
            for (int j = 0; j < 4; j++) {
                const int col = n0 + wn*32 + j*8 + 2*r;
                float2 lo; lo.x = acc[i][j][0]; lo.y = acc[i][j][1];
                float2 hi; hi.x = acc[i][j][2]; hi.y = acc[i][j][3];
                *(float2*)(C + (size_t)row * N + col)     = lo;
                *(float2*)(C + (size_t)(row+8) * N + col) = hi;
            }
        }
    }
#undef LOAD_TILE
}

// ---------------------------------------------------------------------------
// fused RoPE on fp16 q (with sscale folded) and k, in-place
// ---------------------------------------------------------------------------
#define ROPE_NQ (MTOT*NH*64)
#define ROPE_NK (MTOT*KVH*64)
#define ROPE_TOT (ROPE_NQ + ROPE_NK)

__global__ void rope_kernel(__half* __restrict__ qkv,
                            const float* __restrict__ cs,
                            const float* __restrict__ sn)
{
    int idx = blockIdx.x * 256 + threadIdx.x;
    if (idx < ROPE_NQ) {
        int d = idx & 63;
        int h = (idx >> 6) % NH;
        int t = idx / (NH << 6);
        __half* row = qkv + (size_t)t * QKVW + h * HD;
        int s = t & (SEQ - 1);
        float x1 = __half2float(row[d]), x2 = __half2float(row[d + 64]);
        row[d]      = __float2half((x1 * cs[s*HD + d]      - x2 * sn[s*HD + d])      * SSCALE);
        row[d + 64] = __float2half((x2 * cs[s*HD + d + 64] + x1 * sn[s*HD + d + 64]) * SSCALE);
    } else if ((idx -= ROPE_NQ) < ROPE_NK) {
        int d = idx & 63;
        int h = (idx >> 6) % KVH;
        int t = idx / (KVH << 6);
        __half* row = qkv + (size_t)t * QKVW + KOFF + h * HD;
        int s = t & (SEQ - 1);
        float x1 = __half2float(row[d]), x2 = __half2float(row[d + 64]);
        row[d]      = __float2half(x1 * cs[s*HD + d]      - x2 * sn[s*HD + d]);
        row[d + 64] = __float2half(x2 * cs[s*HD + d + 64] + x1 * sn[s*HD + d + 64]);
    }
}

// ---------------------------------------------------------------------------
// Flash attention v2 (FA2 layout): fp16 mma, register-resident P.
// Br=Bc=128, D=128. 256 threads, 8 warps; each warp owns 16 full rows.
// K/V double-buffered cp.async; V via ldmatrix.trans.
// ---------------------------------------------------------------------------
#define FH 136
#define TILE_B (128*FH*2)                 // 34816 bytes
#define SQ_B 0
#define SK_B(s) (TILE_B*(1 + 2*(s)))
#define SV_B(s) (TILE_B*(2 + 2*(s)))
#define FLASH_SMEM (5*TILE_B)

__global__ void __launch_bounds__(256, 1) flash_mma_kernel(
    const __half* __restrict__ qkv, __half* __restrict__ ctx)
{
    extern __shared__ char smc[];
    const uint32_t smb = smem_u32(smc);

    const int b = blockIdx.z, h = blockIdx.y;
    const int qb = (int)gridDim.x - 1 - (int)blockIdx.x;   // long CTAs first
    const int kh = h >> 2;
    const int tid = threadIdx.x;
    const int warp = tid >> 5, lane = tid & 31;
    const int qd = lane >> 2, r4 = lane & 3;

    const int lmt = lane >> 3, lmr = lane & 7;
    const uint32_t lmoff  = (uint32_t)(((((lmt & 1) << 3) | lmr) * FH + ((lmt >> 1) << 3)) * 2);
    const uint32_t lmoffT = (uint32_t)(((lmr + ((lmt >> 1) << 3)) * FH + ((lmt & 1) << 3)) * 2);

    const int grow0 = qb * 128;

    // ---- prologue: Q + K0 + V0 in one group ----
    {
        const __half* qb_ = qkv + (size_t)(b*SEQ + qb*128) * QKVW + h * HD;
        const __half* kb_ = qkv + (size_t)(b*SEQ) * QKVW + KOFF + kh * HD;
        const __half* vb_ = qkv + (size_t)(b*SEQ) * QKVW + VOFF + kh * HD;
#pragma unroll
        for (int l = 0; l < 8; l++) {
            int idx = tid + l*256;
            int row = idx >> 4, ch = (idx & 15) << 3;
            uint32_t so = (uint32_t)((row*FH + ch)*2);
            cp_async16(smb + SQ_B    + so, qb_ + (size_t)row * QKVW + ch);
            cp_async16(smb + SK_B(0) + so, kb_ + (size_t)row * QKVW + ch);
            cp_async16(smb + SV_B(0) + so, vb_ + (size_t)row * QKVW + ch);
        }
        cp_commit();
    }

    float m_r0 = -1e30f, m_r1 = -1e30f, l_r0 = 0.f, l_r1 = 0.f;
    float oacc[16][4];
#pragma unroll
    for (int j = 0; j < 16; j++)
        oacc[j][0]=oacc[j][1]=oacc[j][2]=oacc[j][3]=0.f;

    for (int jb = 0; jb <= qb; jb++) {
        cp_wait0();
        __syncthreads();

        if (jb < qb) {
            const int nb = (jb + 1) & 1;
            const __half* kb_ = qkv + (size_t)(b*SEQ + (jb+1)*128) * QKVW + KOFF + kh * HD;
            const __half* vb_ = qkv + (size_t)(b*SEQ + (jb+1)*128) * QKVW + VOFF + kh * HD;
            const uint32_t skn = smb + (uint32_t)SK_B(nb);
            const uint32_t svn = smb + (uint32_t)SV_B(nb);
#pragma unroll
            for (int l = 0; l < 8; l++) {
                int idx = tid + l*256;
                int row = idx >> 4, ch = (idx & 15) << 3;
                uint32_t so = (uint32_t)((row*FH + ch)*2);
                cp_async16(skn + so, kb_ + (size_t)row * QKVW + ch);
                cp_async16(svn + so, vb_ + (size_t)row * QKVW + ch);
            }
            cp_commit();
        }

        const uint32_t sK = smb + (uint32_t)SK_B(jb & 1);
        const uint32_t sV = smb + (uint32_t)SV_B(jb & 1);

        // ---- QK: warp rows warp*16..+15 x all 128 cols ----
        float sc[16][4];
#pragma unroll
        for (int j = 0; j < 16; j++)
            sc[j][0]=sc[j][1]=sc[j][2]=sc[j][3]=0.f;

        const uint32_t aQ0 = smb + (uint32_t)(SQ_B + (warp*16)*FH*2) + lmoff;
#pragma unroll
        for (int ks = 0; ks < 8; ks++) {
            const uint32_t kk2 = (uint32_t)(ks*32);
            uint32_t qa[4];
            LDSM4(qa[0], qa[1], qa[2], qa[3], aQ0 + kk2);
#pragma unroll
            for (int jt = 0; jt < 8; jt++) {
                uint32_t kb2[2][2];
                LDSM4(kb2[0][0], kb2[1][0], kb2[0][1], kb2[1][1],
                      sK + (uint32_t)((jt*16)*FH*2) + lmoff + kk2);
                mma_f16(sc[jt*2],   qa, kb2[0]);
                mma_f16(sc[jt*2+1], qa, kb2[1]);
            }
        }

        // ---- causal mask ----
        const int col0 = jb * 128;
        if (jb == qb) {
            const int rg0 = grow0 + warp*16 + qd;
#pragma unroll
            for (int j = 0; j < 16; j++) {
                int cg = col0 + j*8 + 2*r4;
                if (cg     > rg0)     sc[j][0] = -1e30f;
                if (cg + 1 > rg0)     sc[j][1] = -1e30f;
                if (cg     > rg0 + 8) sc[j][2] = -1e30f;
                if (cg + 1 > rg0 + 8) sc[j][3] = -1e30f;
            }
        }

        // ---- warp-local softmax ----
        float mx0 = sc[0][0], mx1 = sc[0][2];
#pragma unroll
        for (int j = 0; j < 16; j++) {
            mx0 = fmaxf(mx0, fmaxf(sc[j][0], sc[j][1]));
            mx1 = fmaxf(mx1, fmaxf(sc[j][2], sc[j][3]));
        }
        mx0 = fmaxf(mx0, __shfl_xor_sync(0xffffffffu, mx0, 1));
        mx0 = fmaxf(mx0, __shfl_xor_sync(0xffffffffu, mx0, 2));
        mx1 = fmaxf(mx1, __shfl_xor_sync(0xffffffffu, mx1, 1));
        mx1 = fmaxf(mx1, __shfl_xor_sync(0xffffffffu, mx1, 2));
        const float mn0 = fmaxf(m_r0, mx0);
        const float mn1 = fmaxf(m_r1, mx1);
        const float corr0 = __expf(m_r0 - mn0);
        const float corr1 = __expf(m_r1 - mn1);
        m_r0 = mn0; m_r1 = mn1;

        float ls0 = 0.f, ls1 = 0.f;
#pragma unroll
        for (int j = 0; j < 16; j++) {
            sc[j][0] = __expf(sc[j][0] - mn0); ls0 += sc[j][0];
            sc[j][1] = __expf(sc[j][1] - mn0); ls0 += sc[j][1];
            sc[j][2] = __expf(sc[j][2] - mn1); ls1 += sc[j][2];
            sc[j][3] = __expf(sc[j][3] - mn1); ls1 += sc[j][3];
        }
        ls0 += __shfl_xor_sync(0xffffffffu, ls0, 1);
        ls0 += __shfl_xor_sync(0xffffffffu, ls0, 2);
        ls1 += __shfl_xor_sync(0xffffffffu, ls1, 1);
        ls1 += __shfl_xor_sync(0xffffffffu, ls1, 2);
        l_r0 = l_r0 * corr0 + ls0;
        l_r1 = l_r1 * corr1 + ls1;
#pragma unroll
        for (int j = 0; j < 16; j++) {
            oacc[j][0] *= corr0; oacc[j][1] *= corr0;
            oacc[j][2] *= corr1; oacc[j][3] *= corr1;
        }

        // ---- PV: A = P (registers), B = V via ldmatrix.trans ----
#pragma unroll
        for (int c = 0; c < 8; c++) {
            uint32_t pa[4];
            {
                __half2 t0 = __floats2half2_rn(sc[2*c][0],   sc[2*c][1]);
                __half2 t1 = __floats2half2_rn(sc[2*c][2],   sc[2*c][3]);
                __half2 t2 = __floats2half2_rn(sc[2*c+1][0], sc[2*c+1][1]);
                __half2 t3 = __floats2half2_rn(sc[2*c+1][2], sc[2*c+1][3]);
                pa[0] = *(uint32_t*)&t0; pa[1] = *(uint32_t*)&t1;
                pa[2] = *(uint32_t*)&t2; pa[3] = *(uint32_t*)&t3;
            }
            const uint32_t vrow = sV + (uint32_t)((c*16)*FH*2) + lmoffT;
#pragma unroll
            for (int dt = 0; dt < 8; dt++) {
                uint32_t vb2[2][2];
                LDSM4T(vb2[0][0], vb2[1][0], vb2[0][1], vb2[1][1],
                       vrow + (uint32_t)((dt*16)*2));
                mma_f16(oacc[dt*2],   pa, vb2[0]);
                mma_f16(oacc[dt*2+1], pa, vb2[1]);
            }
        }
    }

    // ---- epilogue: normalize, store fp16 ctx ----
    const float inv0 = 1.f / l_r0;
    const float inv1 = 1.f / l_r1;
    const int row = warp*16 + qd;
    __half* d0 = ctx + ((size_t)(b*SEQ + grow0 + row  ) * NH + h) * HD;
    __half* d1 = ctx + ((size_t)(b*SEQ + grow0 + row+8) * NH + h) * HD;
#pragma unroll
    for (int j = 0; j < 16; j++) {
        const int col = j*8 + 2*r4;
        *(__half2*)(d0 + col) = __floats2half2_rn(oacc[j][0]*inv0, oacc[j][1]*inv0);
        *(__half2*)(d1 + col) = __floats2half2_rn(oacc[j][2]*inv1, oacc[j][3]*inv1);
    }
}

// ---------------------------------------------------------------------------
extern "C" void kernel_launch(void* const* d_in, const int* in_sizes, int n_in,
                              void* d_out, int out_size)
{
    const float* hs   = (const float*)d_in[0];
    const float* cosp = (const float*)d_in[1];
    const float* sinp = (const float*)d_in[2];
    const float* Wq   = (const float*)d_in[3];
    const float* Wk   = (const float*)d_in[4];
    const float* Wv   = (const float*)d_in[5];
    const float* Wo   = (const float*)d_in[6];
    float* out = (float*)d_out;

    __half *qkv, *ctx, *hs_h, *wqkv, *wo;
    cudaGetSymbolAddress((void**)&qkv,  g_qkv);
    cudaGetSymbolAddress((void**)&ctx,  g_ctx);
    cudaGetSymbolAddress((void**)&hs_h, g_hs);
    cudaGetSymbolAddress((void**)&wqkv, g_wqkv);
    cudaGetSymbolAddress((void**)&wo,   g_wo);

    cudaFuncSetAttribute(gemm_mma, cudaFuncAttributeMaxDynamicSharedMemorySize,
                         (int)GEMM_SMEM);
    cudaFuncSetAttribute(flash_mma_kernel, cudaFuncAttributeMaxDynamicSharedMemorySize,
                         (int)FLASH_SMEM);

    const int M = MTOT;  // 4096

    // 1) fp32 -> fp16 conversion of all inputs
    round5_kernel<<<(N4_TOT + 255)/256, 256>>>(hs, Wq, Wk, Wv, Wo,
                                               hs_h, wqkv, wo);

    // 2) fused QKV projection (128x128 CTA, 2 CTAs/SM)
    gemm_mma<<<dim3(QKVW/128, M/128), 256, GEMM_SMEM>>>(hs_h, wqkv, qkv,
                                                        M, QKVW, HIDDEN, 1);

    // 3) fused RoPE on q (scaled) and k
    rope_kernel<<<(ROPE_TOT + 255)/256, 256>>>(qkv, cosp, sinp);

    // 4) attention (FA2: register P, warp softmax, dbuf K/V)
    flash_mma_kernel<<<dim3(SEQ/128, NH, BATCH), 256, FLASH_SMEM>>>(qkv, ctx);

    // 5) output projection (128x128 CTA, 2 CTAs/SM, fp32 output)
    gemm_mma<<<dim3(HIDDEN/128, M/128), 256, GEMM_SMEM>>>(ctx, wo, out,
                                                          M, HIDDEN, HIDDEN, 0);
}

// round 17
// speedup vs baseline: 1.0149x; 1.0054x over previous
#include <cuda_runtime.h>
#include <cuda_fp16.h>
#include <math.h>
#include <stdint.h>

#define BATCH 2
#define SEQ 2048
#define HIDDEN 2048
#define NH 16
#define KVH 4
#define HD 128
#define MTOT (BATCH*SEQ)
#define QKVW 3072
#define KOFF 2048
#define VOFF 2560
#define SSCALE 0.08838834764831845f
#define LOG2E  1.4426950408889634f

// scratch (no allocation allowed -> device globals), all fp16
__device__ __align__(16) __half g_qkv[MTOT*QKVW];
__device__ __align__(16) __half g_ctx[MTOT*HIDDEN];
__device__ __align__(16) __half g_hs[MTOT*HIDDEN];
__device__ __align__(16) __half g_wqkv[QKVW*HIDDEN];
__device__ __align__(16) __half g_wo[HIDDEN*HIDDEN];

// ===========================================================================
// helpers
// ===========================================================================
__device__ __forceinline__ uint32_t smem_u32(const void* p) {
    uint32_t a;
    asm("{ .reg .u64 t; cvta.to.shared.u64 t, %1; cvt.u32.u64 %0, t; }"
        : "=r"(a) : "l"(p));
    return a;
}
__device__ __forceinline__ void cp_async16(uint32_t saddr, const void* gaddr) {
    asm volatile("cp.async.cg.shared.global [%0], [%1], 16;"
                 :: "r"(saddr), "l"(gaddr));
}
__device__ __forceinline__ void cp_commit() {
    asm volatile("cp.async.commit_group;" ::: "memory");
}
__device__ __forceinline__ void cp_wait1() {
    asm volatile("cp.async.wait_group 1;" ::: "memory");
}
__device__ __forceinline__ void cp_wait0() {
    asm volatile("cp.async.wait_group 0;" ::: "memory");
}
__device__ __forceinline__ float ex2(float x) {
    float r;
    asm("ex2.approx.f32 %0, %1;" : "=f"(r) : "f"(x));
    return r;
}
// D += A*B : fp16 m16n8k16, fp32 accumulate
__device__ __forceinline__ void mma_f16(float* d, const uint32_t* a, const uint32_t* b) {
    asm volatile(
        "mma.sync.aligned.m16n8k16.row.col.f32.f16.f16.f32 "
        "{%0,%1,%2,%3}, {%4,%5,%6,%7}, {%8,%9}, {%0,%1,%2,%3};"
        : "+f"(d[0]), "+f"(d[1]), "+f"(d[2]), "+f"(d[3])
        : "r"(a[0]), "r"(a[1]), "r"(a[2]), "r"(a[3]), "r"(b[0]), "r"(b[1]));
}
#define LDSM4(r0,r1,r2,r3,addr)                                              \
    asm volatile("ldmatrix.sync.aligned.m8n8.x4.shared.b16 {%0,%1,%2,%3}, [%4];" \
        : "=r"(r0), "=r"(r1), "=r"(r2), "=r"(r3) : "r"(addr))
#define LDSM4T(r0,r1,r2,r3,addr)                                             \
    asm volatile("ldmatrix.sync.aligned.m8n8.x4.trans.shared.b16 {%0,%1,%2,%3}, [%4];" \
        : "=r"(r0), "=r"(r1), "=r"(r2), "=r"(r3) : "r"(addr))

// ===========================================================================
// fused fp16 conversion pass: hs -> g_hs, [Wq|Wk|Wv] -> g_wqkv, Wo -> g_wo
// ===========================================================================
#define N4_HS  (MTOT*HIDDEN/4)
#define N4_WQ  (HIDDEN*HIDDEN/4)
#define N4_WKV (KVH*HD*HIDDEN/4)
#define N4_TOT (N4_HS + 2*N4_WQ + 2*N4_WKV)

__global__ void round5_kernel(
    const float* __restrict__ hs, const float* __restrict__ wq,
    const float* __restrict__ wk, const float* __restrict__ wv,
    const float* __restrict__ wo,
    __half* __restrict__ dhs, __half* __restrict__ dwqkv,
    __half* __restrict__ dwo)
{
    int i = blockIdx.x * 256 + threadIdx.x;
    if (i >= N4_TOT) return;
    const float* src; __half* dst; int j = i;
    if (j < N4_HS)                  { src = hs; dst = dhs; }
    else if ((j -= N4_HS) < N4_WQ)  { src = wq; dst = dwqkv; }
    else if ((j -= N4_WQ) < N4_WKV) { src = wk; dst = dwqkv + (size_t)KOFF*HIDDEN; }
    else if ((j -= N4_WKV) < N4_WKV){ src = wv; dst = dwqkv + (size_t)VOFF*HIDDEN; }
    else { j -= N4_WKV; src = wo; dst = dwo; }
    float4 v = ((const float4*)src)[j];
    ((__half2*)dst)[2*j]   = __floats2half2_rn(v.x, v.y);
    ((__half2*)dst)[2*j+1] = __floats2half2_rn(v.z, v.w);
}

// ===========================================================================
// fp16 mma.sync GEMM with ldmatrix. CTA 128x128, BK=64 halves, 3-stage
// cp.async, 256 threads (8 warps, 2x4 grid, warp tile 64x32).
// smem 110.6KB; with carveout=100% -> 2 CTAs/SM; launch_bounds caps regs 128.
// ===========================================================================
#define BKH 64
#define APADH 72
#define STAGE_HALVES ((128+128)*APADH)
#define NSTAGE 3
#define GEMM_SMEM (NSTAGE*STAGE_HALVES*2)

__global__ void __launch_bounds__(256, 2) gemm_mma(
    const __half* __restrict__ A, const __half* __restrict__ B,
    void* __restrict__ Cv, int M, int N, int K, int store_half)
{
    extern __shared__ __half smh[];
    const uint32_t smb = smem_u32(smh);

    const int tid  = threadIdx.x;
    const int warp = tid >> 5, lane = tid & 31;
    const int wm = warp >> 2, wn = warp & 3;
    const int m0 = blockIdx.y << 7, n0 = blockIdx.x << 7;
    const int q = lane >> 2, r = lane & 3;

    const int lmt = lane >> 3, lmr = lane & 7;
    const uint32_t lmoff = (uint32_t)((((lmt & 1) << 3 | lmr) * APADH + ((lmt >> 1) << 3)) * 2);

    float acc[4][4][4];
#pragma unroll
    for (int i = 0; i < 4; i++)
#pragma unroll
        for (int j = 0; j < 4; j++)
            acc[i][j][0]=acc[i][j][1]=acc[i][j][2]=acc[i][j][3]=0.f;

    const int arow0 = tid >> 3, ach = (tid & 7) << 3;

#define LOAD_TILE(s, kt) do {                                               \
    const uint32_t sA_ = smb + (uint32_t)(s)*STAGE_HALVES*2;                \
    const uint32_t sB_ = sA_ + 128*APADH*2;                                 \
    const int koff = (kt) * BKH;                                            \
    _Pragma("unroll")                                                       \
    for (int l_ = 0; l_ < 4; l_++) {                                        \
        int row = arow0 + l_*32;                                            \
        cp_async16(sA_ + (uint32_t)(row*APADH + ach)*2,                     \
                   A + (size_t)(m0 + row) * K + koff + ach);                \
        cp_async16(sB_ + (uint32_t)(row*APADH + ach)*2,                     \
                   B + (size_t)(n0 + row) * K + koff + ach);                \
    } } while (0)

    const int KT = K / BKH;
    LOAD_TILE(0, 0); cp_commit();
    LOAD_TILE(1, 1); cp_commit();
    cp_wait1();
    __syncthreads();

    for (int kt = 0; kt < KT; kt++) {
        const int nxt = kt + 2;
        if (nxt < KT) {
            int s = nxt - (nxt/NSTAGE)*NSTAGE;
            LOAD_TILE(s, nxt);
        }
        cp_commit();

        const int cs = kt - (kt/NSTAGE)*NSTAGE;
        const uint32_t sAb = smb + (uint32_t)cs*STAGE_HALVES*2;
        const uint32_t sBb = sAb + 128*APADH*2;

#pragma unroll
        for (int ks = 0; ks < 4; ks++) {
            const uint32_t kk2 = (uint32_t)(ks*32);
            uint32_t afr[4][4], bfr[4][2];
#pragma unroll
            for (int i = 0; i < 4; i++)
                LDSM4(afr[i][0], afr[i][1], afr[i][2], afr[i][3],
                      sAb + (uint32_t)((wm*64 + i*16)*APADH*2) + lmoff + kk2);
            LDSM4(bfr[0][0], bfr[1][0], bfr[0][1], bfr[1][1],
                  sBb + (uint32_t)((wn*32)*APADH*2) + lmoff + kk2);
            LDSM4(bfr[2][0], bfr[3][0], bfr[2][1], bfr[3][1],
                  sBb + (uint32_t)((wn*32 + 16)*APADH*2) + lmoff + kk2);
#pragma unroll
            for (int i = 0; i < 4; i++)
#pragma unroll
                for (int j = 0; j < 4; j++)
                    mma_f16(acc[i][j], afr[i], bfr[j]);
        }

        cp_wait1();
        __syncthreads();
    }

    if (store_half) {
        __half* C = (__half*)Cv;
#pragma unroll
        for (int i = 0; i < 4; i++) {
            const int row = m0 + wm*64 + i*16 + q;
#pragma unroll
            for (int j = 0; j < 4; j++) {
                const int col = n0 + wn*32 + j*8 + 2*r;
                *(__half2*)(C + (size_t)row * N + col) =
                    __floats2half2_rn(acc[i][j][0], acc[i][j][1]);
                *(__half2*)(C + (size_t)(row+8) * N + col) =
                    __floats2half2_rn(acc[i][j][2], acc[i][j][3]);
            }
        }
    } else {
        float* C = (float*)Cv;
#pragma unroll
        for (int i = 0; i < 4; i++) {
            const int row = m0 + wm*64 + i*16 + q;
#pragma unroll
            for (int j = 0; j < 4; j++) {
                const int col = n0 + wn*32 + j*8 + 2*r;
                float2 lo; lo.x = acc[i][j][0]; lo.y = acc[i][j][1];
                float2 hi; hi.x = acc[i][j][2]; hi.y = acc[i][j][3];
                *(float2*)(C + (size_t)row * N + col)     = lo;
                *(float2*)(C + (size_t)(row+8) * N + col) = hi;
            }
        }
    }
#undef LOAD_TILE
}

// ---------------------------------------------------------------------------
// fused RoPE on fp16 q (with sscale*log2e folded) and k, in-place
// ---------------------------------------------------------------------------
#define ROPE_NQ (MTOT*NH*64)
#define ROPE_NK (MTOT*KVH*64)
#define ROPE_TOT (ROPE_NQ + ROPE_NK)

__global__ void rope_kernel(__half* __restrict__ qkv,
                            const float* __restrict__ cs,
                            const float* __restrict__ sn)
{
    int idx = blockIdx.x * 256 + threadIdx.x;
    if (idx < ROPE_NQ) {
        int d = idx & 63;
        int h = (idx >> 6) % NH;
        int t = idx / (NH << 6);
        __half* row = qkv + (size_t)t * QKVW + h * HD;
        int s = t & (SEQ - 1);
        const float qs = SSCALE * LOG2E;   // fold 1/sqrt(d) and log2(e) into Q
        float x1 = __half2float(row[d]), x2 = __half2float(row[d + 64]);
        row[d]      = __float2half((x1 * cs[s*HD + d]      - x2 * sn[s*HD + d])      * qs);
        row[d + 64] = __float2half((x2 * cs[s*HD + d + 64] + x1 * sn[s*HD + d + 64]) * qs);
    } else if ((idx -= ROPE_NQ) < ROPE_NK) {
        int d = idx & 63;
        int h = (idx >> 6) % KVH;
        int t = idx / (KVH << 6);
        __half* row = qkv + (size_t)t * QKVW + KOFF + h * HD;
        int s = t & (SEQ - 1);
        float x1 = __half2float(row[d]), x2 = __half2float(row[d + 64]);
        row[d]      = __float2half(x1 * cs[s*HD + d]      - x2 * sn[s*HD + d]);
        row[d + 64] = __float2half(x2 * cs[s*HD + d + 64] + x1 * sn[s*HD + d + 64]);
    }
}

// ---------------------------------------------------------------------------
// Flash attention v2 (FA2 layout): fp16 mma, register-resident P.
// Br=Bc=128, D=128. 256 threads, 8 warps; each warp owns 16 full rows.
// Scores are in log2 domain (Q pre-scaled by log2e) -> softmax uses ex2.
// ---------------------------------------------------------------------------
#define FH 136
#define TILE_B (128*FH*2)
#define SQ_B 0
#define SK_B(s) (TILE_B*(1 + 2*(s)))
#define SV_B(s) (TILE_B*(2 + 2*(s)))
#define FLASH_SMEM (5*TILE_B)

__global__ void __launch_bounds__(256, 1) flash_mma_kernel(
    const __half* __restrict__ qkv, __half* __restrict__ ctx)
{
    extern __shared__ char smc[];
    const uint32_t smb = smem_u32(smc);

    const int b = blockIdx.z, h = blockIdx.y;
    const int qb = (int)gridDim.x - 1 - (int)blockIdx.x;   // long CTAs first
    const int kh = h >> 2;
    const int tid = threadIdx.x;
    const int warp = tid >> 5, lane = tid & 31;
    const int qd = lane >> 2, r4 = lane & 3;

    const int lmt = lane >> 3, lmr = lane & 7;
    const uint32_t lmoff  = (uint32_t)(((((lmt & 1) << 3) | lmr) * FH + ((lmt >> 1) << 3)) * 2);
    const uint32_t lmoffT = (uint32_t)(((lmr + ((lmt >> 1) << 3)) * FH + ((lmt & 1) << 3)) * 2);

    const int grow0 = qb * 128;

    // ---- prologue: Q + K0 + V0 in one group ----
    {
        const __half* qb_ = qkv + (size_t)(b*SEQ + qb*128) * QKVW + h * HD;
        const __half* kb_ = qkv + (size_t)(b*SEQ) * QKVW + KOFF + kh * HD;
        const __half* vb_ = qkv + (size_t)(b*SEQ) * QKVW + VOFF + kh * HD;
#pragma unroll
        for (int l = 0; l < 8; l++) {
            int idx = tid + l*256;
            int row = idx >> 4, ch = (idx & 15) << 3;
            uint32_t so = (uint32_t)((row*FH + ch)*2);
            cp_async16(smb + SQ_B    + so, qb_ + (size_t)row * QKVW + ch);
            cp_async16(smb + SK_B(0) + so, kb_ + (size_t)row * QKVW + ch);
            cp_async16(smb + SV_B(0) + so, vb_ + (size_t)row * QKVW + ch);
        }
        cp_commit();
    }

    float m_r0 = -1e30f, m_r1 = -1e30f, l_r0 = 0.f, l_r1 = 0.f;
    float oacc[16][4];
#pragma unroll
    for (int j = 0; j < 16; j++)
        oacc[j][0]=oacc[j][1]=oacc[j][2]=oacc[j][3]=0.f;

    for (int jb = 0; jb <= qb; jb++) {
        cp_wait0();
        __syncthreads();

        if (jb < qb) {
            const int nb = (jb + 1) & 1;
            const __half* kb_ = qkv + (size_t)(b*SEQ + (jb+1)*128) * QKVW + KOFF + kh * HD;
            const __half* vb_ = qkv + (size_t)(b*SEQ + (jb+1)*128) * QKVW + VOFF + kh * HD;
            const uint32_t skn = smb + (uint32_t)SK_B(nb);
            const uint32_t svn = smb + (uint32_t)SV_B(nb);
#pragma unroll
            for (int l = 0; l < 8; l++) {
                int idx = tid + l*256;
                int row = idx >> 4, ch = (idx & 15) << 3;
                uint32_t so = (uint32_t)((row*FH + ch)*2);
                cp_async16(skn + so, kb_ + (size_t)row * QKVW + ch);
                cp_async16(svn + so, vb_ + (size_t)row * QKVW + ch);
            }
            cp_commit();
        }

        const uint32_t sK = smb + (uint32_t)SK_B(jb & 1);
        const uint32_t sV = smb + (uint32_t)SV_B(jb & 1);

        // ---- QK: warp rows warp*16..+15 x all 128 cols ----
        float sc[16][4];
#pragma unroll
        for (int j = 0; j < 16; j++)
            sc[j][0]=sc[j][1]=sc[j][2]=sc[j][3]=0.f;

        const uint32_t aQ0 = smb + (uint32_t)(SQ_B + (warp*16)*FH*2) + lmoff;
#pragma unroll
        for (int ks = 0; ks < 8; ks++) {
            const uint32_t kk2 = (uint32_t)(ks*32);
            uint32_t qa[4];
            LDSM4(qa[0], qa[1], qa[2], qa[3], aQ0 + kk2);
#pragma unroll
            for (int jt = 0; jt < 8; jt++) {
                uint32_t kb2[2][2];
                LDSM4(kb2[0][0], kb2[1][0], kb2[0][1], kb2[1][1],
                      sK + (uint32_t)((jt*16)*FH*2) + lmoff + kk2);
                mma_f16(sc[jt*2],   qa, kb2[0]);
                mma_f16(sc[jt*2+1], qa, kb2[1]);
            }
        }

        // ---- causal mask ----
        const int col0 = jb * 128;
        if (jb == qb) {
            const int rg0 = grow0 + warp*16 + qd;
#pragma unroll
            for (int j = 0; j < 16; j++) {
                int cg = col0 + j*8 + 2*r4;
                if (cg     > rg0)     sc[j][0] = -1e30f;
                if (cg + 1 > rg0)     sc[j][1] = -1e30f;
                if (cg     > rg0 + 8) sc[j][2] = -1e30f;
                if (cg + 1 > rg0 + 8) sc[j][3] = -1e30f;
            }
        }

        // ---- warp-local softmax (log2 domain, ex2) ----
        float mx0 = sc[0][0], mx1 = sc[0][2];
#pragma unroll
        for (int j = 0; j < 16; j++) {
            mx0 = fmaxf(mx0, fmaxf(sc[j][0], sc[j][1]));
            mx1 = fmaxf(mx1, fmaxf(sc[j][2], sc[j][3]));
        }
        mx0 = fmaxf(mx0, __shfl_xor_sync(0xffffffffu, mx0, 1));
        mx0 = fmaxf(mx0, __shfl_xor_sync(0xffffffffu, mx0, 2));
        mx1 = fmaxf(mx1, __shfl_xor_sync(0xffffffffu, mx1, 1));
        mx1 = fmaxf(mx1, __shfl_xor_sync(0xffffffffu, mx1, 2));
        const float mn0 = fmaxf(m_r0, mx0);
        const float mn1 = fmaxf(m_r1, mx1);
        const float corr0 = ex2(m_r0 - mn0);
        const float corr1 = ex2(m_r1 - mn1);
        m_r0 = mn0; m_r1 = mn1;

        float ls0 = 0.f, ls1 = 0.f;
#pragma unroll
        for (int j = 0; j < 16; j++) {
            sc[j][0] = ex2(sc[j][0] - mn0); ls0 += sc[j][0];
            sc[j][1] = ex2(sc[j][1] - mn0); ls0 += sc[j][1];
            sc[j][2] = ex2(sc[j][2] - mn1); ls1 += sc[j][2];
            sc[j][3] = ex2(sc[j][3] - mn1); ls1 += sc[j][3];
        }
        ls0 += __shfl_xor_sync(0xffffffffu, ls0, 1);
        ls0 += __shfl_xor_sync(0xffffffffu, ls0, 2);
        ls1 += __shfl_xor_sync(0xffffffffu, ls1, 1);
        ls1 += __shfl_xor_sync(0xffffffffu, ls1, 2);
        l_r0 = l_r0 * corr0 + ls0;
        l_r1 = l_r1 * corr1 + ls1;
#pragma unroll
        for (int j = 0; j < 16; j++) {
            oacc[j][0] *= corr0; oacc[j][1] *= corr0;
            oacc[j][2] *= corr1; oacc[j][3] *= corr1;
        }

        // ---- PV: A = P (registers), B = V via ldmatrix.trans ----
#pragma unroll
        for (int c = 0; c < 8; c++) {
            uint32_t pa[4];
            {
                __half2 t0 = __floats2half2_rn(sc[2*c][0],   sc[2*c][1]);
                __half2 t1 = __floats2half2_rn(sc[2*c][2],   sc[2*c][3]);
                __half2 t2 = __floats2half2_rn(sc[2*c+1][0], sc[2*c+1][1]);
                __half2 t3 = __floats2half2_rn(sc[2*c+1][2], sc[2*c+1][3]);
                pa[0] = *(uint32_t*)&t0; pa[1] = *(uint32_t*)&t1;
                pa[2] = *(uint32_t*)&t2; pa[3] = *(uint32_t*)&t3;
            }
            const uint32_t vrow = sV + (uint32_t)((c*16)*FH*2) + lmoffT;
#pragma unroll
            for (int dt = 0; dt < 8; dt++) {
                uint32_t vb2[2][2];
                LDSM4T(vb2[0][0], vb2[1][0], vb2[0][1], vb2[1][1],
                       vrow + (uint32_t)((dt*16)*2));
                mma_f16(oacc[dt*2],   pa, vb2[0]);
                mma_f16(oacc[dt*2+1], pa, vb2[1]);
            }
        }
    }

    // ---- epilogue: normalize, store fp16 ctx ----
    const float inv0 = 1.f / l_r0;
    const float inv1 = 1.f / l_r1;
    const int row = warp*16 + qd;
    __half* d0 = ctx + ((size_t)(b*SEQ + grow0 + row  ) * NH + h) * HD;
    __half* d1 = ctx + ((size_t)(b*SEQ + grow0 + row+8) * NH + h) * HD;
#pragma unroll
    for (int j = 0; j < 16; j++) {
        const int col = j*8 + 2*r4;
        *(__half2*)(d0 + col) = __floats2half2_rn(oacc[j][0]*inv0, oacc[j][1]*inv0);
        *(__half2*)(d1 + col) = __floats2half2_rn(oacc[j][2]*inv1, oacc[j][3]*inv1);
    }
}

// ---------------------------------------------------------------------------
extern "C" void kernel_launch(void* const* d_in, const int* in_sizes, int n_in,
                              void* d_out, int out_size)
{
    const float* hs   = (const float*)d_in[0];
    const float* cosp = (const float*)d_in[1];
    const float* sinp = (const float*)d_in[2];
    const float* Wq   = (const float*)d_in[3];
    const float* Wk   = (const float*)d_in[4];
    const float* Wv   = (const float*)d_in[5];
    const float* Wo   = (const float*)d_in[6];
    float* out = (float*)d_out;

    __half *qkv, *ctx, *hs_h, *wqkv, *wo;
    cudaGetSymbolAddress((void**)&qkv,  g_qkv);
    cudaGetSymbolAddress((void**)&ctx,  g_ctx);
    cudaGetSymbolAddress((void**)&hs_h, g_hs);
    cudaGetSymbolAddress((void**)&wqkv, g_wqkv);
    cudaGetSymbolAddress((void**)&wo,   g_wo);

    // opt-in max dynamic smem AND force max shared-memory carveout so the
    // 110.6KB gemm can actually co-reside 2 CTAs/SM.
    cudaFuncSetAttribute(gemm_mma, cudaFuncAttributeMaxDynamicSharedMemorySize,
                         (int)GEMM_SMEM);
    cudaFuncSetAttribute(gemm_mma, cudaFuncAttributePreferredSharedMemoryCarveout,
                         100);
    cudaFuncSetAttribute(flash_mma_kernel, cudaFuncAttributeMaxDynamicSharedMemorySize,
                         (int)FLASH_SMEM);
    cudaFuncSetAttribute(flash_mma_kernel, cudaFuncAttributePreferredSharedMemoryCarveout,
                         100);

    const int M = MTOT;  // 4096

    // 1) fp32 -> fp16 conversion of all inputs
    round5_kernel<<<(N4_TOT + 255)/256, 256>>>(hs, Wq, Wk, Wv, Wo,
                                               hs_h, wqkv, wo);

    // 2) fused QKV projection (128x128 CTA, target 2 CTAs/SM)
    gemm_mma<<<dim3(QKVW/128, M/128), 256, GEMM_SMEM>>>(hs_h, wqkv, qkv,
                                                        M, QKVW, HIDDEN, 1);

    // 3) fused RoPE on q (scaled by sscale*log2e) and k
    rope_kernel<<<(ROPE_TOT + 255)/256, 256>>>(qkv, cosp, sinp);

    // 4) attention (FA2: register P, warp softmax, ex2, dbuf K/V)
    flash_mma_kernel<<<dim3(SEQ/128, NH, BATCH), 256, FLASH_SMEM>>>(qkv, ctx);

    // 5) output projection (128x128 CTA, target 2 CTAs/SM, fp32 output)
    gemm_mma<<<dim3(HIDDEN/128, M/128), 256, GEMM_SMEM>>>(ctx, wo, out,
                                                          M, HIDDEN, HIDDEN, 0);
}